// round 1
// baseline (speedup 1.0000x reference)
#include <cuda_runtime.h>
#include <math.h>

// Problem constants
#define Hd   256      // hidden
#define Ed   128      // embedding
#define Bd   32       // batch
#define Sd   128      // src len
#define Td   64       // trg len
#define Vd   32000    // vocab
#define G4   1024     // 4*H

// ---------------- device scratch (static, no runtime alloc) ----------------
__device__ float g_h0[Hd * Bd];                 // h ping  [u*32+b]
__device__ float g_h1[Hd * Bd];                 // h pong
__device__ float g_c [Hd * Bd];                 // c state [u*32+b]
__device__ float g_xe[Sd * G4 * Bd];            // encoder xproj [t][r][b] (bias folded)
__device__ float g_xd[(Td - 1) * G4 * Bd];      // decoder xproj [t][r][b]
__device__ float g_hs[(Td - 1) * Bd * Hd];      // decoder hidden history [(t*32+b)][u]

__device__ __forceinline__ float sigm(float x) { return 1.0f / (1.0f + __expf(-x)); }

__device__ __forceinline__ float2 ffma2(float2 a, float2 b, float2 c) {
    unsigned long long au, bu, cu, du;
    au = *reinterpret_cast<unsigned long long*>(&a);
    bu = *reinterpret_cast<unsigned long long*>(&b);
    cu = *reinterpret_cast<unsigned long long*>(&c);
    asm("fma.rn.f32x2 %0, %1, %2, %3;" : "=l"(du) : "l"(au), "l"(bu), "l"(cu));
    return *reinterpret_cast<float2*>(&du);
}

// ---------------- init: zero prediction[:,0,:], h0, c ----------------
__global__ void init_kernel(float* __restrict__ out) {
    int idx = blockIdx.x * blockDim.x + threadIdx.x;
    int stride = gridDim.x * blockDim.x;
    const int total = Bd * Vd;
    for (int i = idx; i < total; i += stride) {
        int b = i / Vd, v = i - b * Vd;
        out[(size_t)b * Td * Vd + v] = 0.0f;
    }
    if (idx < Hd * Bd) { g_h0[idx] = 0.0f; g_c[idx] = 0.0f; }
}

// ---------------- input projection: xproj[t][r][b] = bias[r] + emb[tok[b,t]] . Wih[r] ----------------
// grid: (32 row-tiles of 32, Tn), 256 threads
__global__ void proj_kernel(const int* __restrict__ tok, int tok_stride,
                            const float* __restrict__ emb,
                            const float* __restrict__ Wih,
                            const float* __restrict__ bias,
                            int which)   // 0 -> g_xe, 1 -> g_xd
{
    __shared__ float x_s[Ed * Bd];   // [e][b]
    __shared__ float w_s[32 * Ed];   // [rlocal][e]
    float* xproj = which ? g_xd : g_xe;

    int t = blockIdx.y;
    int rbase = blockIdx.x * 32;
    int tid = threadIdx.x;

    for (int idx = tid; idx < Bd * Ed; idx += 256) {
        int b = idx >> 7, e = idx & 127;
        x_s[e * Bd + b] = emb[(size_t)tok[b * tok_stride + t] * Ed + e];
    }
    for (int idx = tid; idx < 32 * Ed; idx += 256) {
        w_s[idx] = Wih[(size_t)rbase * Ed + idx];
    }
    __syncthreads();

    int lane = tid & 31;
    int wr = tid >> 5;   // 0..7, each handles 4 rows
    float acc[4];
#pragma unroll
    for (int i = 0; i < 4; i++) acc[i] = bias[rbase + wr * 4 + i];

#pragma unroll 4
    for (int k = 0; k < Ed; k++) {
        float xv = x_s[k * Bd + lane];
#pragma unroll
        for (int i = 0; i < 4; i++)
            acc[i] = fmaf(w_s[(wr * 4 + i) * Ed + k], xv, acc[i]);
    }

    float* o = xproj + ((size_t)t * G4 + rbase + wr * 4) * Bd + lane;
#pragma unroll
    for (int i = 0; i < 4; i++) o[(size_t)i * Bd] = acc[i];
}

// ---------------- one recurrent LSTM step ----------------
// grid 128 blocks x 256 threads; block owns 2 hidden units (all 4 gates)
__global__ void step_kernel(const float* __restrict__ Whh,
                            int which,      // xproj: 0 enc, 1 dec
                            int t,          // step within phase
                            int parity,     // read buffer selector
                            int dec_t)      // >=0: write hs slot
{
    __shared__ float h_s[Hd * Bd];   // [k][b] 32KB
    __shared__ float g_s[256];

    const float* hin  = parity ? g_h1 : g_h0;
    float*       hout = parity ? g_h0 : g_h1;
    const float* xprojT = (which ? g_xd : g_xe) + (size_t)t * G4 * Bd;

    int tid = threadIdx.x;
    {
        const float4* s4 = (const float4*)hin;
        float4* d4 = (float4*)h_s;
        for (int i = tid; i < Hd * Bd / 4; i += 256) d4[i] = s4[i];
    }
    __syncthreads();

    int b  = tid & 31;
    int q  = (tid >> 5) & 3;
    int iu = tid >> 7;
    int u  = blockIdx.x * 2 + iu;
    int r  = q * Hd + u;

    float acc = xprojT[(size_t)r * Bd + b];
    const float4* w4 = (const float4*)(Whh + (size_t)r * Hd);
#pragma unroll 8
    for (int k4 = 0; k4 < Hd / 4; k4++) {
        float4 w = w4[k4];
        int k = k4 * 4;
        acc = fmaf(w.x, h_s[(k + 0) * Bd + b], acc);
        acc = fmaf(w.y, h_s[(k + 1) * Bd + b], acc);
        acc = fmaf(w.z, h_s[(k + 2) * Bd + b], acc);
        acc = fmaf(w.w, h_s[(k + 3) * Bd + b], acc);
    }
    g_s[tid] = acc;   // layout [iu*128 + q*32 + b] == tid
    __syncthreads();

    if (tid < 64) {
        int iu2 = tid >> 5, b2 = tid & 31;
        int u2 = blockIdx.x * 2 + iu2;
        float gi = g_s[iu2 * 128 +  0 + b2];
        float gf = g_s[iu2 * 128 + 32 + b2];
        float gg = g_s[iu2 * 128 + 64 + b2];
        float go = g_s[iu2 * 128 + 96 + b2];
        int idx = u2 * Bd + b2;
        float c = sigm(gf) * g_c[idx] + sigm(gi) * tanhf(gg);
        float h = sigm(go) * tanhf(c);
        g_c[idx]  = c;
        hout[idx] = h;
        if (dec_t >= 0)
            g_hs[((size_t)dec_t * Bd + b2) * Hd + u2] = h;
    }
}

// ---------------- finalize: hn, cn ([b][u]) appended after prediction ----------------
__global__ void finalize_kernel(float* __restrict__ out) {
    int idx = blockIdx.x * blockDim.x + threadIdx.x;
    if (idx < Hd * Bd) {
        int b = idx >> 8, u = idx & 255;
        size_t base = (size_t)Bd * Td * Vd;
        out[base + idx]           = g_h1[u * Bd + b];   // hn (final step writes g_h1)
        out[base + Hd * Bd + idx] = g_c [u * Bd + b];   // cn
    }
}

// ---------------- FC: out[b, t+1, v] = hs[(t*32+b)] . Wfc[v] + bfc[v] ----------------
#define FBM 64
#define FBN 128
#define FBK 16
#define FMROWS ((Td - 1) * Bd)   // 2016

__global__ __launch_bounds__(256) void fc_kernel(const float* __restrict__ W,    // [V][H]
                                                 const float* __restrict__ bias, // [V]
                                                 float* __restrict__ out)
{
    __shared__ float As[FBM][FBK];   // [m][k]
    __shared__ float Bs[FBK][FBN];   // [k][v]

    int tid = threadIdx.x;
    int mbase = blockIdx.y * FBM;
    int vbase = blockIdx.x * FBN;
    int tx = tid & 15;      // N dir: 8 cols each
    int ty = tid >> 4;      // M dir: 4 rows each

    float2 acc[4][4];
#pragma unroll
    for (int i = 0; i < 4; i++)
#pragma unroll
        for (int j = 0; j < 4; j++) acc[i][j] = make_float2(0.f, 0.f);

    int lrow = tid >> 2;            // 0..63
    int lcol = (tid & 3) << 2;      // 0,4,8,12

    for (int kk = 0; kk < Hd; kk += FBK) {
        {   // A tile (guarded tail)
            int m = mbase + lrow;
            float4 v = make_float4(0.f, 0.f, 0.f, 0.f);
            if (m < FMROWS) v = *(const float4*)(g_hs + (size_t)m * Hd + kk + lcol);
            *(float4*)&As[lrow][lcol] = v;
        }
#pragma unroll
        for (int rep = 0; rep < 2; rep++) {   // B tile
            int vr = rep * 64 + lrow;
            float4 v = *(const float4*)(W + (size_t)(vbase + vr) * Hd + kk + lcol);
            Bs[lcol + 0][vr] = v.x;
            Bs[lcol + 1][vr] = v.y;
            Bs[lcol + 2][vr] = v.z;
            Bs[lcol + 3][vr] = v.w;
        }
        __syncthreads();

#pragma unroll
        for (int k = 0; k < FBK; k++) {
            float4 b0 = *(const float4*)&Bs[k][tx * 8];
            float4 b1 = *(const float4*)&Bs[k][tx * 8 + 4];
            float2 bp0 = make_float2(b0.x, b0.y);
            float2 bp1 = make_float2(b0.z, b0.w);
            float2 bp2 = make_float2(b1.x, b1.y);
            float2 bp3 = make_float2(b1.z, b1.w);
#pragma unroll
            for (int i = 0; i < 4; i++) {
                float a = As[ty * 4 + i][k];
                float2 ad = make_float2(a, a);
                acc[i][0] = ffma2(ad, bp0, acc[i][0]);
                acc[i][1] = ffma2(ad, bp1, acc[i][1]);
                acc[i][2] = ffma2(ad, bp2, acc[i][2]);
                acc[i][3] = ffma2(ad, bp3, acc[i][3]);
            }
        }
        __syncthreads();
    }

    // epilogue
    const float* bi = bias + vbase + tx * 8;
    float4 bv0 = *(const float4*)(bi);
    float4 bv1 = *(const float4*)(bi + 4);
#pragma unroll
    for (int i = 0; i < 4; i++) {
        int m = mbase + ty * 4 + i;
        if (m >= FMROWS) continue;
        int b = m & 31, t = m >> 5;
        float* o = out + ((size_t)b * Td + t + 1) * Vd + vbase + tx * 8;
        float4 r0, r1;
        r0.x = acc[i][0].x + bv0.x;  r0.y = acc[i][0].y + bv0.y;
        r0.z = acc[i][1].x + bv0.z;  r0.w = acc[i][1].y + bv0.w;
        r1.x = acc[i][2].x + bv1.x;  r1.y = acc[i][2].y + bv1.y;
        r1.z = acc[i][3].x + bv1.z;  r1.w = acc[i][3].y + bv1.w;
        *(float4*)(o)     = r0;
        *(float4*)(o + 4) = r1;
    }
}

// ---------------- launch ----------------
extern "C" void kernel_launch(void* const* d_in, const int* in_sizes, int n_in,
                              void* d_out, int out_size)
{
    const int*   src     = (const int*)  d_in[0];
    const int*   trg     = (const int*)  d_in[1];
    const float* emb_src = (const float*)d_in[2];
    const float* Wih_e   = (const float*)d_in[3];
    const float* Whh_e   = (const float*)d_in[4];
    const float* b_e     = (const float*)d_in[5];
    const float* emb_trg = (const float*)d_in[6];
    const float* Wih_d   = (const float*)d_in[7];
    const float* Whh_d   = (const float*)d_in[8];
    const float* b_d     = (const float*)d_in[9];
    const float* Wfc     = (const float*)d_in[10];
    const float* bfc     = (const float*)d_in[11];
    float* out = (float*)d_out;

    init_kernel<<<512, 256>>>(out);

    // encoder input projections for all 128 timesteps
    proj_kernel<<<dim3(32, Sd), 256>>>(src, Sd, emb_src, Wih_e, b_e, 0);
    // encoder recurrence
    for (int s = 0; s < Sd; s++)
        step_kernel<<<128, 256>>>(Whh_e, 0, s, s & 1, -1);

    // decoder input projections for 63 timesteps
    proj_kernel<<<dim3(32, Td - 1), 256>>>(trg, Td, emb_trg, Wih_d, b_d, 1);
    // decoder recurrence (writes hs history)
    for (int s = 0; s < Td - 1; s++)
        step_kernel<<<128, 256>>>(Whh_d, 1, s, (Sd + s) & 1, s);

    finalize_kernel<<<32, 256>>>(out);

    // vocab projection
    fc_kernel<<<dim3(Vd / FBN, (FMROWS + FBM - 1) / FBM), 256>>>(Wfc, bfc, out);
}

// round 2
// speedup vs baseline: 1.3342x; 1.3342x over previous
#include <cuda_runtime.h>
#include <math.h>

// Problem constants
#define Hd   256      // hidden
#define Ed   128      // embedding
#define Bd   32       // batch
#define Sd   128      // src len
#define Td   64       // trg len
#define Vd   32000    // vocab
#define G4   1024     // 4*H

#define NBLK 128
#define NTHR 256
#define NSTEPS (Sd + Td - 1)   // 191

// ---------------- device scratch (static, no runtime alloc) ----------------
__device__ float g_h0[Hd * Bd];                 // h ping  [u][b]
__device__ float g_h1[Hd * Bd];                 // h pong
__device__ float g_xe[Sd * G4 * Bd];            // encoder xproj [t][r][b] (bias folded)
__device__ float g_xd[(Td - 1) * G4 * Bd];      // decoder xproj [t][r][b]
__device__ float g_hs[(Td - 1) * Bd * Hd];      // decoder hidden history [(t*32+b)][u]
__device__ unsigned g_bar;                      // global barrier counter

__device__ __forceinline__ float sigm(float x) { return 1.0f / (1.0f + __expf(-x)); }

__device__ __forceinline__ float2 ffma2(float2 a, float2 b, float2 c) {
    unsigned long long au, bu, cu, du;
    au = *reinterpret_cast<unsigned long long*>(&a);
    bu = *reinterpret_cast<unsigned long long*>(&b);
    cu = *reinterpret_cast<unsigned long long*>(&c);
    asm("fma.rn.f32x2 %0, %1, %2, %3;" : "=l"(du) : "l"(au), "l"(bu), "l"(cu));
    return *reinterpret_cast<float2*>(&du);
}

__device__ __forceinline__ unsigned ld_acquire_gpu(unsigned* p) {
    unsigned v;
    asm volatile("ld.acquire.gpu.u32 %0, [%1];" : "=r"(v) : "l"(p));
    return v;
}

// ---------------- init: zero prediction[:,0,:] and barrier ----------------
__global__ void init_kernel(float* __restrict__ out) {
    int idx = blockIdx.x * blockDim.x + threadIdx.x;
    int stride = gridDim.x * blockDim.x;
    const int total = Bd * Vd;
    for (int i = idx; i < total; i += stride) {
        int b = i / Vd, v = i - b * Vd;
        out[(size_t)b * Td * Vd + v] = 0.0f;
    }
    if (idx == 0) g_bar = 0u;
}

// ---------------- input projection: xproj[t][r][b] = bias[r] + emb[tok[b,t]] . Wih[r] ----------------
__global__ void proj_kernel(const int* __restrict__ tok, int tok_stride,
                            const float* __restrict__ emb,
                            const float* __restrict__ Wih,
                            const float* __restrict__ bias,
                            int which)   // 0 -> g_xe, 1 -> g_xd
{
    __shared__ float x_s[Ed * Bd];   // [e][b]
    __shared__ float w_s[32 * Ed];   // [rlocal][e]
    float* xproj = which ? g_xd : g_xe;

    int t = blockIdx.y;
    int rbase = blockIdx.x * 32;
    int tid = threadIdx.x;

    for (int idx = tid; idx < Bd * Ed; idx += 256) {
        int b = idx >> 7, e = idx & 127;
        x_s[e * Bd + b] = emb[(size_t)tok[b * tok_stride + t] * Ed + e];
    }
    for (int idx = tid; idx < 32 * Ed; idx += 256) {
        w_s[idx] = Wih[(size_t)rbase * Ed + idx];
    }
    __syncthreads();

    int lane = tid & 31;
    int wr = tid >> 5;   // 0..7, each handles 4 rows
    float acc[4];
#pragma unroll
    for (int i = 0; i < 4; i++) acc[i] = bias[rbase + wr * 4 + i];

#pragma unroll 4
    for (int k = 0; k < Ed; k++) {
        float xv = x_s[k * Bd + lane];
#pragma unroll
        for (int i = 0; i < 4; i++)
            acc[i] = fmaf(w_s[(wr * 4 + i) * Ed + k], xv, acc[i]);
    }

    float* o = xproj + ((size_t)t * G4 + rbase + wr * 4) * Bd + lane;
#pragma unroll
    for (int i = 0; i < 4; i++) o[(size_t)i * Bd] = acc[i];
}

// ---------------- persistent recurrence kernel ----------------
// 128 blocks x 256 threads; block j owns units [2j, 2j+2) (all 4 gates = 8 rows).
// c-state lives in smem for all 191 steps; weights staged in smem per phase;
// h ping-pongs through global with one grid barrier per step.
__global__ void __launch_bounds__(NTHR, 1) recur_kernel(
    const float* __restrict__ Whh_e,
    const float* __restrict__ Whh_d,
    float* __restrict__ out)
{
    __shared__ float  h_s[Hd * Bd];     // 32KB, [k][b]
    __shared__ float  w_s[8 * Hd];      // 8KB, [row8][k], current phase
    __shared__ float2 g_sm[8][16];      // gate pairs [row8][bpair]
    __shared__ float2 c_sm[32];         // c for 2 units x 16 bpairs

    const int tid = threadIdx.x;
    const int u0  = blockIdx.x * 2;

    const int bp   = tid & 15;          // batch pair 0..15
    const int ks   = (tid >> 4) & 1;    // k-split half
    const int row8 = tid >> 5;          // warp id = local row 0..7
    const int q    = row8 & 3;          // gate
    const int iu   = row8 >> 2;         // unit within block
    const int row_global = q * Hd + u0 + iu;

    // stage encoder weights
    for (int i = tid; i < 8 * Hd; i += NTHR) {
        int r8 = i >> 8, k = i & 255;
        int qq = r8 & 3, iuu = r8 >> 2;
        w_s[i] = Whh_e[(size_t)(qq * Hd + u0 + iuu) * Hd + k];
    }
    // h0 = 0, c0 = 0
    for (int i = tid; i < Hd * Bd; i += NTHR) h_s[i] = 0.0f;
    if (tid < 32) c_sm[tid] = make_float2(0.f, 0.f);
    __syncthreads();

    const float2* hp = (const float2*)h_s;   // [k*16 + bp]

    for (int step = 0; step < NSTEPS; step++) {
        const bool dec = (step >= Sd);
        const int  t   = dec ? step - Sd : step;
        const float* xproj = dec ? g_xd : g_xe;

        // phase switch: swap in decoder weights
        if (step == Sd) {
            for (int i = tid; i < 8 * Hd; i += NTHR) {
                int r8 = i >> 8, k = i & 255;
                int qq = r8 & 3, iuu = r8 >> 2;
                w_s[i] = Whh_d[(size_t)(qq * Hd + u0 + iuu) * Hd + k];
            }
            __syncthreads();
        }

        // stage h (written last step) into smem
        if (step > 0) {
            const float4* src = (const float4*)(((step - 1) & 1) ? g_h1 : g_h0);
            float4* dst = (float4*)h_s;
#pragma unroll
            for (int i = 0; i < 8; i++)
                dst[tid + i * NTHR] = src[tid + i * NTHR];
        }
        __syncthreads();

        // gate GEMV: row_global . h  over half of k
        float2 acc = make_float2(0.f, 0.f);
        if (ks == 0)
            acc = *(const float2*)(xproj + ((size_t)t * G4 + row_global) * Bd + bp * 2);
        const float4* wrow = (const float4*)(w_s + row8 * Hd + ks * 128);
        const int kbase = ks * 128;
#pragma unroll 8
        for (int k4 = 0; k4 < 32; k4++) {
            float4 w = wrow[k4];
            int k = kbase + k4 * 4;
            float2 h0v = hp[(k + 0) * 16 + bp];
            float2 h1v = hp[(k + 1) * 16 + bp];
            float2 h2v = hp[(k + 2) * 16 + bp];
            float2 h3v = hp[(k + 3) * 16 + bp];
            acc = ffma2(make_float2(w.x, w.x), h0v, acc);
            acc = ffma2(make_float2(w.y, w.y), h1v, acc);
            acc = ffma2(make_float2(w.z, w.z), h2v, acc);
            acc = ffma2(make_float2(w.w, w.w), h3v, acc);
        }
        // reduce k-split halves (partner lane = lane ^ 16, same warp)
        acc.x += __shfl_xor_sync(0xffffffff, acc.x, 16);
        acc.y += __shfl_xor_sync(0xffffffff, acc.y, 16);
        if (ks == 0) g_sm[row8][bp] = acc;
        __syncthreads();

        // elementwise LSTM cell for the 2 owned units
        float* hw = (step & 1) ? g_h1 : g_h0;
        if (tid < 32) {
            int iu2 = tid >> 4, bp2 = tid & 15;
            float2 gi = g_sm[iu2 * 4 + 0][bp2];
            float2 gf = g_sm[iu2 * 4 + 1][bp2];
            float2 gg = g_sm[iu2 * 4 + 2][bp2];
            float2 go = g_sm[iu2 * 4 + 3][bp2];
            float2 c = c_sm[tid];
            c.x = sigm(gf.x) * c.x + sigm(gi.x) * tanhf(gg.x);
            c.y = sigm(gf.y) * c.y + sigm(gi.y) * tanhf(gg.y);
            float2 h;
            h.x = sigm(go.x) * tanhf(c.x);
            h.y = sigm(go.y) * tanhf(c.y);
            c_sm[tid] = c;
            int u = u0 + iu2;
            *(float2*)(hw + u * Bd + bp2 * 2) = h;
            if (dec) {
                int b0 = bp2 * 2;
                g_hs[((size_t)t * Bd + b0)     * Hd + u] = h.x;
                g_hs[((size_t)t * Bd + b0 + 1) * Hd + u] = h.y;
            }
            if (step == NSTEPS - 1) {
                size_t base = (size_t)Bd * Td * Vd;
                int b0 = bp2 * 2;
                out[base + (size_t)b0 * Hd + u]       = h.x;   // hn [b][u]
                out[base + (size_t)(b0 + 1) * Hd + u] = h.y;
                out[base + (size_t)Bd * Hd + (size_t)b0 * Hd + u]       = c.x;  // cn
                out[base + (size_t)Bd * Hd + (size_t)(b0 + 1) * Hd + u] = c.y;
            }
        }
        __syncthreads();

        // grid barrier (monotonic counter; classic fence+atomic+spin)
        if (step < NSTEPS - 1) {
            if (tid == 0) {
                __threadfence();
                atomicAdd(&g_bar, 1u);
                unsigned target = (unsigned)(NBLK * (step + 1));
                while (ld_acquire_gpu(&g_bar) < target) { }
            }
            __syncthreads();
        }
    }
}

// ---------------- FC: out[b, t+1, v] = hs[(t*32+b)] . Wfc[v] + bfc[v] ----------------
#define FBM 64
#define FBN 128
#define FBK 16
#define FMROWS ((Td - 1) * Bd)   // 2016

__global__ __launch_bounds__(256) void fc_kernel(const float* __restrict__ W,    // [V][H]
                                                 const float* __restrict__ bias, // [V]
                                                 float* __restrict__ out)
{
    __shared__ float As[FBM][FBK];   // [m][k]
    __shared__ float Bs[FBK][FBN];   // [k][v]

    int tid = threadIdx.x;
    int mbase = blockIdx.y * FBM;
    int vbase = blockIdx.x * FBN;
    int tx = tid & 15;      // N dir: 8 cols each
    int ty = tid >> 4;      // M dir: 4 rows each

    float2 acc[4][4];
#pragma unroll
    for (int i = 0; i < 4; i++)
#pragma unroll
        for (int j = 0; j < 4; j++) acc[i][j] = make_float2(0.f, 0.f);

    int lrow = tid >> 2;            // 0..63
    int lcol = (tid & 3) << 2;      // 0,4,8,12

    for (int kk = 0; kk < Hd; kk += FBK) {
        {   // A tile (guarded tail)
            int m = mbase + lrow;
            float4 v = make_float4(0.f, 0.f, 0.f, 0.f);
            if (m < FMROWS) v = *(const float4*)(g_hs + (size_t)m * Hd + kk + lcol);
            *(float4*)&As[lrow][lcol] = v;
        }
#pragma unroll
        for (int rep = 0; rep < 2; rep++) {   // B tile
            int vr = rep * 64 + lrow;
            float4 v = *(const float4*)(W + (size_t)(vbase + vr) * Hd + kk + lcol);
            Bs[lcol + 0][vr] = v.x;
            Bs[lcol + 1][vr] = v.y;
            Bs[lcol + 2][vr] = v.z;
            Bs[lcol + 3][vr] = v.w;
        }
        __syncthreads();

#pragma unroll
        for (int k = 0; k < FBK; k++) {
            float4 b0 = *(const float4*)&Bs[k][tx * 8];
            float4 b1 = *(const float4*)&Bs[k][tx * 8 + 4];
            float2 bp0 = make_float2(b0.x, b0.y);
            float2 bp1 = make_float2(b0.z, b0.w);
            float2 bp2 = make_float2(b1.x, b1.y);
            float2 bp3 = make_float2(b1.z, b1.w);
#pragma unroll
            for (int i = 0; i < 4; i++) {
                float a = As[ty * 4 + i][k];
                float2 ad = make_float2(a, a);
                acc[i][0] = ffma2(ad, bp0, acc[i][0]);
                acc[i][1] = ffma2(ad, bp1, acc[i][1]);
                acc[i][2] = ffma2(ad, bp2, acc[i][2]);
                acc[i][3] = ffma2(ad, bp3, acc[i][3]);
            }
        }
        __syncthreads();
    }

    // epilogue
    const float* bi = bias + vbase + tx * 8;
    float4 bv0 = *(const float4*)(bi);
    float4 bv1 = *(const float4*)(bi + 4);
#pragma unroll
    for (int i = 0; i < 4; i++) {
        int m = mbase + ty * 4 + i;
        if (m >= FMROWS) continue;
        int b = m & 31, t = m >> 5;
        float* o = out + ((size_t)b * Td + t + 1) * Vd + vbase + tx * 8;
        float4 r0, r1;
        r0.x = acc[i][0].x + bv0.x;  r0.y = acc[i][0].y + bv0.y;
        r0.z = acc[i][1].x + bv0.z;  r0.w = acc[i][1].y + bv0.w;
        r1.x = acc[i][2].x + bv1.x;  r1.y = acc[i][2].y + bv1.y;
        r1.z = acc[i][3].x + bv1.z;  r1.w = acc[i][3].y + bv1.w;
        *(float4*)(o)     = r0;
        *(float4*)(o + 4) = r1;
    }
}

// ---------------- launch ----------------
extern "C" void kernel_launch(void* const* d_in, const int* in_sizes, int n_in,
                              void* d_out, int out_size)
{
    const int*   src     = (const int*)  d_in[0];
    const int*   trg     = (const int*)  d_in[1];
    const float* emb_src = (const float*)d_in[2];
    const float* Wih_e   = (const float*)d_in[3];
    const float* Whh_e   = (const float*)d_in[4];
    const float* b_e     = (const float*)d_in[5];
    const float* emb_trg = (const float*)d_in[6];
    const float* Wih_d   = (const float*)d_in[7];
    const float* Whh_d   = (const float*)d_in[8];
    const float* b_d     = (const float*)d_in[9];
    const float* Wfc     = (const float*)d_in[10];
    const float* bfc     = (const float*)d_in[11];
    float* out = (float*)d_out;

    init_kernel<<<512, 256>>>(out);

    // input projections for all timesteps (parallel over t)
    proj_kernel<<<dim3(32, Sd), 256>>>(src, Sd, emb_src, Wih_e, b_e, 0);
    proj_kernel<<<dim3(32, Td - 1), 256>>>(trg, Td, emb_trg, Wih_d, b_d, 1);

    // full recurrence (encoder + decoder) in one persistent kernel
    recur_kernel<<<NBLK, NTHR>>>(Whh_e, Whh_d, out);

    // vocab projection
    fc_kernel<<<dim3(Vd / FBN, (FMROWS + FBM - 1) / FBM), 256>>>(Wfc, bfc, out);
}

// round 8
// speedup vs baseline: 2.1801x; 1.6340x over previous
#include <cuda_runtime.h>
#include <cuda_bf16.h>
#include <math.h>
#include <stdint.h>

// Problem constants
#define Hd   256      // hidden
#define Ed   128      // embedding
#define Bd   32       // batch
#define Sd   128      // src len
#define Td   64       // trg len
#define Vd   32000    // vocab
#define G4   1024     // 4*H

#define NBLK 128
#define NTHR 256
#define NSTEPS (Sd + Td - 1)   // 191

#define MPAD 2048     // padded M for FC (2016 -> 2048)

// ---------------- device scratch (static, no runtime alloc) ----------------
__device__ float g_h0[Hd * Bd];
__device__ float g_h1[Hd * Bd];
__device__ float g_xe[Sd * G4 * Bd];
__device__ float g_xd[(Td - 1) * G4 * Bd];
__device__ float g_hs[(Td - 1) * Bd * Hd];      // [(t*32+b)][u]
__device__ unsigned g_bar;

// bf16 split operands for the FC GEMM
__device__ __nv_bfloat16 g_Whi[Vd * Hd];
__device__ __nv_bfloat16 g_Wlo[Vd * Hd];
__device__ __nv_bfloat16 g_Ahi[MPAD * Hd];
__device__ __nv_bfloat16 g_Alo[MPAD * Hd];

__device__ __forceinline__ float sigm(float x) { return 1.0f / (1.0f + __expf(-x)); }

__device__ __forceinline__ float2 ffma2(float2 a, float2 b, float2 c) {
    unsigned long long au, bu, cu, du;
    au = *reinterpret_cast<unsigned long long*>(&a);
    bu = *reinterpret_cast<unsigned long long*>(&b);
    cu = *reinterpret_cast<unsigned long long*>(&c);
    asm("fma.rn.f32x2 %0, %1, %2, %3;" : "=l"(du) : "l"(au), "l"(bu), "l"(cu));
    return *reinterpret_cast<float2*>(&du);
}

__device__ __forceinline__ unsigned ld_acquire_gpu(unsigned* p) {
    unsigned v;
    asm volatile("ld.acquire.gpu.u32 %0, [%1];" : "=r"(v) : "l"(p));
    return v;
}

__device__ __forceinline__ uint32_t smem_u32(const void* p) {
    uint32_t a;
    asm("{ .reg .u64 t; cvta.to.shared.u64 t, %1; cvt.u32.u64 %0, t; }" : "=r"(a) : "l"(p));
    return a;
}

// ---------------- init ----------------
__global__ void init_kernel(float* __restrict__ out) {
    int idx = blockIdx.x * blockDim.x + threadIdx.x;
    int stride = gridDim.x * blockDim.x;
    const int total = Bd * Vd;
    for (int i = idx; i < total; i += stride) {
        int b = i / Vd, v = i - b * Vd;
        out[(size_t)b * Td * Vd + v] = 0.0f;
    }
    if (idx == 0) g_bar = 0u;
}

// ---------------- input projection ----------------
__global__ void proj_kernel(const int* __restrict__ tok, int tok_stride,
                            const float* __restrict__ emb,
                            const float* __restrict__ Wih,
                            const float* __restrict__ bias,
                            int which) {
    __shared__ float x_s[Ed * Bd];
    __shared__ float w_s[32 * Ed];
    float* xproj = which ? g_xd : g_xe;

    int t = blockIdx.y;
    int rbase = blockIdx.x * 32;
    int tid = threadIdx.x;

    for (int idx = tid; idx < Bd * Ed; idx += 256) {
        int b = idx >> 7, e = idx & 127;
        x_s[e * Bd + b] = emb[(size_t)tok[b * tok_stride + t] * Ed + e];
    }
    for (int idx = tid; idx < 32 * Ed; idx += 256)
        w_s[idx] = Wih[(size_t)rbase * Ed + idx];
    __syncthreads();

    int lane = tid & 31;
    int wr = tid >> 5;
    float acc[4];
#pragma unroll
    for (int i = 0; i < 4; i++) acc[i] = bias[rbase + wr * 4 + i];

#pragma unroll 4
    for (int k = 0; k < Ed; k++) {
        float xv = x_s[k * Bd + lane];
#pragma unroll
        for (int i = 0; i < 4; i++)
            acc[i] = fmaf(w_s[(wr * 4 + i) * Ed + k], xv, acc[i]);
    }

    float* o = xproj + ((size_t)t * G4 + rbase + wr * 4) * Bd + lane;
#pragma unroll
    for (int i = 0; i < 4; i++) o[(size_t)i * Bd] = acc[i];
}

// ---------------- persistent recurrence kernel ----------------
__global__ void __launch_bounds__(NTHR, 1) recur_kernel(
    const float* __restrict__ Whh_e,
    const float* __restrict__ Whh_d,
    float* __restrict__ out)
{
    __shared__ float  h_s[Hd * Bd];
    __shared__ float  w_s[8 * Hd];
    __shared__ float2 g_sm[8][16];
    __shared__ float2 c_sm[32];

    const int tid = threadIdx.x;
    const int u0  = blockIdx.x * 2;

    const int bp   = tid & 15;
    const int ks   = (tid >> 4) & 1;
    const int row8 = tid >> 5;
    const int q    = row8 & 3;
    const int iu   = row8 >> 2;
    const int row_global = q * Hd + u0 + iu;

    for (int i = tid; i < 8 * Hd; i += NTHR) {
        int r8 = i >> 8, k = i & 255;
        int qq = r8 & 3, iuu = r8 >> 2;
        w_s[i] = Whh_e[(size_t)(qq * Hd + u0 + iuu) * Hd + k];
    }
    for (int i = tid; i < Hd * Bd; i += NTHR) h_s[i] = 0.0f;
    if (tid < 32) c_sm[tid] = make_float2(0.f, 0.f);
    __syncthreads();

    const float2* hp = (const float2*)h_s;

    for (int step = 0; step < NSTEPS; step++) {
        const bool dec = (step >= Sd);
        const int  t   = dec ? step - Sd : step;
        const float* xproj = dec ? g_xd : g_xe;

        if (step == Sd) {
            for (int i = tid; i < 8 * Hd; i += NTHR) {
                int r8 = i >> 8, k = i & 255;
                int qq = r8 & 3, iuu = r8 >> 2;
                w_s[i] = Whh_d[(size_t)(qq * Hd + u0 + iuu) * Hd + k];
            }
            __syncthreads();
        }

        if (step > 0) {
            const float4* src = (const float4*)(((step - 1) & 1) ? g_h1 : g_h0);
            float4* dst = (float4*)h_s;
#pragma unroll
            for (int i = 0; i < 8; i++)
                dst[tid + i * NTHR] = src[tid + i * NTHR];
        }
        __syncthreads();

        float2 acc = make_float2(0.f, 0.f);
        if (ks == 0)
            acc = *(const float2*)(xproj + ((size_t)t * G4 + row_global) * Bd + bp * 2);
        const float4* wrow = (const float4*)(w_s + row8 * Hd + ks * 128);
        const int kbase = ks * 128;
#pragma unroll 8
        for (int k4 = 0; k4 < 32; k4++) {
            float4 w = wrow[k4];
            int k = kbase + k4 * 4;
            float2 h0v = hp[(k + 0) * 16 + bp];
            float2 h1v = hp[(k + 1) * 16 + bp];
            float2 h2v = hp[(k + 2) * 16 + bp];
            float2 h3v = hp[(k + 3) * 16 + bp];
            acc = ffma2(make_float2(w.x, w.x), h0v, acc);
            acc = ffma2(make_float2(w.y, w.y), h1v, acc);
            acc = ffma2(make_float2(w.z, w.z), h2v, acc);
            acc = ffma2(make_float2(w.w, w.w), h3v, acc);
        }
        acc.x += __shfl_xor_sync(0xffffffff, acc.x, 16);
        acc.y += __shfl_xor_sync(0xffffffff, acc.y, 16);
        if (ks == 0) g_sm[row8][bp] = acc;
        __syncthreads();

        float* hw = (step & 1) ? g_h1 : g_h0;
        if (tid < 32) {
            int iu2 = tid >> 4, bp2 = tid & 15;
            float2 gi = g_sm[iu2 * 4 + 0][bp2];
            float2 gf = g_sm[iu2 * 4 + 1][bp2];
            float2 gg = g_sm[iu2 * 4 + 2][bp2];
            float2 go = g_sm[iu2 * 4 + 3][bp2];
            float2 c = c_sm[tid];
            c.x = sigm(gf.x) * c.x + sigm(gi.x) * tanhf(gg.x);
            c.y = sigm(gf.y) * c.y + sigm(gi.y) * tanhf(gg.y);
            float2 h;
            h.x = sigm(go.x) * tanhf(c.x);
            h.y = sigm(go.y) * tanhf(c.y);
            c_sm[tid] = c;
            int u = u0 + iu2;
            *(float2*)(hw + u * Bd + bp2 * 2) = h;
            if (dec) {
                int b0 = bp2 * 2;
                g_hs[((size_t)t * Bd + b0)     * Hd + u] = h.x;
                g_hs[((size_t)t * Bd + b0 + 1) * Hd + u] = h.y;
            }
            if (step == NSTEPS - 1) {
                size_t base = (size_t)Bd * Td * Vd;
                int b0 = bp2 * 2;
                out[base + (size_t)b0 * Hd + u]       = h.x;
                out[base + (size_t)(b0 + 1) * Hd + u] = h.y;
                out[base + (size_t)Bd * Hd + (size_t)b0 * Hd + u]       = c.x;
                out[base + (size_t)Bd * Hd + (size_t)(b0 + 1) * Hd + u] = c.y;
            }
        }
        __syncthreads();

        if (step < NSTEPS - 1) {
            if (tid == 0) {
                __threadfence();
                atomicAdd(&g_bar, 1u);
                unsigned target = (unsigned)(NBLK * (step + 1));
                while (ld_acquire_gpu(&g_bar) < target) { }
            }
            __syncthreads();
        }
    }
}

// ---------------- bf16 split conversions ----------------
__global__ void convW_kernel(const float* __restrict__ W) {
    int i = blockIdx.x * blockDim.x + threadIdx.x;   // group of 4 floats
    const int total = Vd * Hd / 4;
    if (i >= total) return;
    float4 v = ((const float4*)W)[i];
    __nv_bfloat162 h01, h23, l01, l23;
    h01.x = __float2bfloat16(v.x); l01.x = __float2bfloat16(v.x - __bfloat162float(h01.x));
    h01.y = __float2bfloat16(v.y); l01.y = __float2bfloat16(v.y - __bfloat162float(h01.y));
    h23.x = __float2bfloat16(v.z); l23.x = __float2bfloat16(v.z - __bfloat162float(h23.x));
    h23.y = __float2bfloat16(v.w); l23.y = __float2bfloat16(v.w - __bfloat162float(h23.y));
    ((__nv_bfloat162*)g_Whi)[i * 2]     = h01;
    ((__nv_bfloat162*)g_Whi)[i * 2 + 1] = h23;
    ((__nv_bfloat162*)g_Wlo)[i * 2]     = l01;
    ((__nv_bfloat162*)g_Wlo)[i * 2 + 1] = l23;
}

__global__ void convA_kernel() {
    int i = blockIdx.x * blockDim.x + threadIdx.x;   // group of 4 floats
    const int total = MPAD * Hd / 4;
    if (i >= total) return;
    int m = (i * 4) >> 8;
    float4 v = make_float4(0.f, 0.f, 0.f, 0.f);
    if (m < (Td - 1) * Bd) v = ((const float4*)g_hs)[i];
    __nv_bfloat162 h01, h23, l01, l23;
    h01.x = __float2bfloat16(v.x); l01.x = __float2bfloat16(v.x - __bfloat162float(h01.x));
    h01.y = __float2bfloat16(v.y); l01.y = __float2bfloat16(v.y - __bfloat162float(h01.y));
    h23.x = __float2bfloat16(v.z); l23.x = __float2bfloat16(v.z - __bfloat162float(h23.x));
    h23.y = __float2bfloat16(v.w); l23.y = __float2bfloat16(v.w - __bfloat162float(h23.y));
    ((__nv_bfloat162*)g_Ahi)[i * 2]     = h01;
    ((__nv_bfloat162*)g_Ahi)[i * 2 + 1] = h23;
    ((__nv_bfloat162*)g_Alo)[i * 2]     = l01;
    ((__nv_bfloat162*)g_Alo)[i * 2 + 1] = l23;
}

// ---------------- FC via mma.sync (bf16 split, HMMA) ----------------
// C[2016, 32000] = A[2016,256] . W[32000,256]^T, split hi/lo (3 MMAs).
// BM=128, BN=128, BK=32; 8 warps = 2 (M) x 4 (N); warp tile 64x32.
#define BKC   32
#define NCH   (Hd / BKC)      // 8
#define LDA   40              // smem row stride (bf16) — conflict-free for ldmatrix
#define FMROWS ((Td - 1) * Bd)   // 2016

__device__ __forceinline__ void ldsm_x4(uint32_t* r, uint32_t addr) {
    asm volatile("ldmatrix.sync.aligned.m8n8.x4.shared.b16 {%0,%1,%2,%3}, [%4];"
                 : "=r"(r[0]), "=r"(r[1]), "=r"(r[2]), "=r"(r[3]) : "r"(addr));
}
__device__ __forceinline__ void ldsm_x2(uint32_t* r, uint32_t addr) {
    asm volatile("ldmatrix.sync.aligned.m8n8.x2.shared.b16 {%0,%1}, [%2];"
                 : "=r"(r[0]), "=r"(r[1]) : "r"(addr));
}
__device__ __forceinline__ void mma16816(float* c, const uint32_t* a, const uint32_t* b) {
    asm volatile("mma.sync.aligned.m16n8k16.row.col.f32.bf16.bf16.f32 "
                 "{%0,%1,%2,%3}, {%4,%5,%6,%7}, {%8,%9}, {%0,%1,%2,%3};"
                 : "+f"(c[0]), "+f"(c[1]), "+f"(c[2]), "+f"(c[3])
                 : "r"(a[0]), "r"(a[1]), "r"(a[2]), "r"(a[3]), "r"(b[0]), "r"(b[1]));
}

__global__ void __launch_bounds__(256) fcmma_kernel(const float* __restrict__ bias,
                                                    float* __restrict__ out)
{
    __shared__ __align__(16) __nv_bfloat16 sAh[128 * LDA];
    __shared__ __align__(16) __nv_bfloat16 sAl[128 * LDA];
    __shared__ __align__(16) __nv_bfloat16 sBh[128 * LDA];
    __shared__ __align__(16) __nv_bfloat16 sBl[128 * LDA];
    __shared__ float bias_s[128];

    const int tid = threadIdx.x;
    const int lane = tid & 31;
    const int wid = tid >> 5;
    const int vbase = blockIdx.x * 128;
    const int mbase = blockIdx.y * 128;
    const int warp_m = (wid & 1) * 64;
    const int warp_n = (wid >> 1) * 32;

    if (tid < 32) ((float4*)bias_s)[tid] = ((const float4*)(bias + vbase))[tid];

    const uint32_t uAh = smem_u32(sAh);
    const uint32_t uAl = smem_u32(sAl);
    const uint32_t uBh = smem_u32(sBh);
    const uint32_t uBl = smem_u32(sBl);

    // ldmatrix per-lane address components
    const int arow = warp_m + (lane & 15);
    const int acol = (lane >> 4) << 3;
    const int l16  = lane & 15;
    const int brow = warp_n + (l16 & 7);
    const int bcol = ((l16 >> 3) & 1) << 3;

    float acc[4][4][4];
#pragma unroll
    for (int i = 0; i < 4; i++)
#pragma unroll
        for (int j = 0; j < 4; j++)
#pragma unroll
            for (int r = 0; r < 4; r++) acc[i][j][r] = 0.0f;

    // prefetch ch 0
    uint4 pAh[2], pAl[2], pBh[2], pBl[2];
    int pr[2], pj[2];
#pragma unroll
    for (int s = 0; s < 2; s++) {
        int idx = tid + s * 256;             // 0..511
        pr[s] = idx >> 2; pj[s] = idx & 3;
        const size_t ga = (size_t)(mbase + pr[s]) * Hd + pj[s] * 8;
        const size_t gb = (size_t)(vbase + pr[s]) * Hd + pj[s] * 8;
        pAh[s] = *(const uint4*)(g_Ahi + ga);
        pAl[s] = *(const uint4*)(g_Alo + ga);
        pBh[s] = *(const uint4*)(g_Whi + gb);
        pBl[s] = *(const uint4*)(g_Wlo + gb);
    }

    for (int ch = 0; ch < NCH; ch++) {
        __syncthreads();   // previous compute done
#pragma unroll
        for (int s = 0; s < 2; s++) {
            int o = pr[s] * LDA + pj[s] * 8;
            *(uint4*)(sAh + o) = pAh[s];
            *(uint4*)(sAl + o) = pAl[s];
            *(uint4*)(sBh + o) = pBh[s];
            *(uint4*)(sBl + o) = pBl[s];
        }
        __syncthreads();

        if (ch + 1 < NCH) {
            const int kk = (ch + 1) * BKC;
#pragma unroll
            for (int s = 0; s < 2; s++) {
                const size_t ga = (size_t)(mbase + pr[s]) * Hd + kk + pj[s] * 8;
                const size_t gb = (size_t)(vbase + pr[s]) * Hd + kk + pj[s] * 8;
                pAh[s] = *(const uint4*)(g_Ahi + ga);
                pAl[s] = *(const uint4*)(g_Alo + ga);
                pBh[s] = *(const uint4*)(g_Whi + gb);
                pBl[s] = *(const uint4*)(g_Wlo + gb);
            }
        }

#pragma unroll
        for (int k16 = 0; k16 < BKC; k16 += 16) {
            uint32_t bh[4][2], bl[4][2];
#pragma unroll
            for (int ni = 0; ni < 4; ni++) {
                uint32_t boff = (uint32_t)(((brow + ni * 8) * LDA + k16 + bcol) * 2);
                ldsm_x2(bh[ni], uBh + boff);
                ldsm_x2(bl[ni], uBl + boff);
            }
#pragma unroll
            for (int mi = 0; mi < 4; mi++) {
                uint32_t aoff = (uint32_t)(((arow + mi * 16) * LDA + k16 + acol) * 2);
                uint32_t ah[4], al[4];
                ldsm_x4(ah, uAh + aoff);
                ldsm_x4(al, uAl + aoff);
#pragma unroll
                for (int ni = 0; ni < 4; ni++) {
                    mma16816(acc[mi][ni], ah, bh[ni]);
                    mma16816(acc[mi][ni], ah, bl[ni]);
                    mma16816(acc[mi][ni], al, bh[ni]);
                }
            }
        }
    }

    // epilogue: direct gmem writes with bias
#pragma unroll
    for (int mi = 0; mi < 4; mi++) {
        int gm0 = mbase + warp_m + mi * 16 + (lane >> 2);
#pragma unroll
        for (int ni = 0; ni < 4; ni++) {
            int cloc = warp_n + ni * 8 + ((lane & 3) << 1);
            int gv = vbase + cloc;
            float b0 = bias_s[cloc], b1 = bias_s[cloc + 1];
#pragma unroll
            for (int half = 0; half < 2; half++) {
                int gm = gm0 + half * 8;
                if (gm < FMROWS) {
                    int b = gm & 31, t = gm >> 5;
                    float2 r;
                    r.x = acc[mi][ni][half * 2 + 0] + b0;
                    r.y = acc[mi][ni][half * 2 + 1] + b1;
                    *(float2*)(out + ((size_t)b * Td + t + 1) * Vd + gv) = r;
                }
            }
        }
    }
}

// ---------------- launch ----------------
extern "C" void kernel_launch(void* const* d_in, const int* in_sizes, int n_in,
                              void* d_out, int out_size)
{
    const int*   src     = (const int*)  d_in[0];
    const int*   trg     = (const int*)  d_in[1];
    const float* emb_src = (const float*)d_in[2];
    const float* Wih_e   = (const float*)d_in[3];
    const float* Whh_e   = (const float*)d_in[4];
    const float* b_e     = (const float*)d_in[5];
    const float* emb_trg = (const float*)d_in[6];
    const float* Wih_d   = (const float*)d_in[7];
    const float* Whh_d   = (const float*)d_in[8];
    const float* b_d     = (const float*)d_in[9];
    const float* Wfc     = (const float*)d_in[10];
    const float* bfc     = (const float*)d_in[11];
    float* out = (float*)d_out;

    init_kernel<<<512, 256>>>(out);

    // W split can start immediately (independent of recurrence)
    convW_kernel<<<(Vd * Hd / 4 + 255) / 256, 256>>>(Wfc);

    proj_kernel<<<dim3(32, Sd), 256>>>(src, Sd, emb_src, Wih_e, b_e, 0);
    proj_kernel<<<dim3(32, Td - 1), 256>>>(trg, Td, emb_trg, Wih_d, b_d, 1);

    recur_kernel<<<NBLK, NTHR>>>(Whh_e, Whh_d, out);

    convA_kernel<<<(MPAD * Hd / 4 + 255) / 256, 256>>>();

    fcmma_kernel<<<dim3(Vd / 128, MPAD / 128), 256>>>(bfc, out);
}